// round 14
// baseline (speedup 1.0000x reference)
#include <cuda_runtime.h>
#include <cuda_fp16.h>
#include <math.h>

#define NN 1024
#define KK 32
#define HH 256
#define DEn 128
#define NE 8
#define NHn 8
#define DHn 32
#define FF 512
#define SS 260   // 16B-aligned padded slot stride

typedef unsigned long long ull;

__device__ int   g_te[NN * 2];
__device__ float g_tg[NN * 2];

// prepacked fp16 weights: k-pairs (W[k][j], W[k+1][j]) in one half2 (uint)
#define OFF_WE   0u
#define OFF_WN   131072u
#define OFF_WM   655360u
#define OFF_WQKV 1179648u
#define OFF_WO   1966080u
#define OFF_W1N  2228224u
#define OFF_W2N  2752512u
#define OFF_W1E  3276800u
#define OFF_W2E  3801088u
#define WP_TOTAL 4325376u
__device__ unsigned int g_wph[WP_TOTAL];

__device__ __forceinline__ float gelu_f(float x) {
    float u = 0.7978845608028654f * (x + 0.044715f * x * x * x);
    float e = __expf(2.f * u);
    float t = 1.f - __fdividef(2.f, e + 1.f);
    return 0.5f * x * (1.f + t);
}
__device__ __forceinline__ ull pk2(float lo, float hi) {
    ull r; asm("mov.b64 %0,{%1,%2};" : "=l"(r) : "f"(lo), "f"(hi)); return r;
}
__device__ __forceinline__ void upk2(ull v, float& lo, float& hi) {
    asm("mov.b64 {%0,%1},%2;" : "=f"(lo), "=f"(hi) : "l"(v));
}
__device__ __forceinline__ void fma2(ull& d, ull a, ull b) {
    asm("fma.rn.f32x2 %0,%1,%2,%0;" : "+l"(d) : "l"(a), "l"(b));
}
__device__ __forceinline__ float fold(ull v) {
    float lo, hi; upk2(v, lo, hi); return lo + hi;
}
// half2 (as uint) -> packed f32x2
__device__ __forceinline__ ull h2f2(unsigned int h) {
    __half2 hh = *reinterpret_cast<const __half2*>(&h);
    float2 f = __half22float2(hh);
    return pk2(f.x, f.y);
}

__device__ __forceinline__ float bsum256(float v, float* red) {
    #pragma unroll
    for (int o = 16; o; o >>= 1) v += __shfl_xor_sync(0xffffffffu, v, o);
    int tid = threadIdx.x;
    if ((tid & 31) == 0) red[tid >> 5] = v;
    __syncthreads();
    float s = red[0] + red[1] + red[2] + red[3] + red[4] + red[5] + red[6] + red[7];
    __syncthreads();
    return s;
}

// ---- 8-row x 4-col f32x2 GEMM, fp16 weights, pipelined weight prefetch ----
__device__ __forceinline__ void initacc(ull acc[8][4], const float* bias, int cq) {
    float4 b = *(const float4*)(bias + cq);
    ull b0 = pk2(b.x, 0.f), b1 = pk2(b.y, 0.f), b2 = pk2(b.z, 0.f), b3 = pk2(b.w, 0.f);
    #pragma unroll
    for (int r = 0; r < 8; r++) {
        acc[r][0] = b0; acc[r][1] = b1; acc[r][2] = b2; acc[r][3] = b3;
    }
}

__device__ __forceinline__ void fma_quad(ull acc[8][4], const float* ip, const int inS,
                                         uint4 ha, uint4 hb) {
    ull wa0 = h2f2(ha.x), wa1 = h2f2(ha.y), wa2 = h2f2(ha.z), wa3 = h2f2(ha.w);
    ull wb0 = h2f2(hb.x), wb1 = h2f2(hb.y), wb2 = h2f2(hb.z), wb3 = h2f2(hb.w);
    ulonglong2 x[8];
    #pragma unroll
    for (int r = 0; r < 8; r++) x[r] = *(const ulonglong2*)(ip + r * inS);
    #pragma unroll
    for (int r = 0; r < 8; r++) {
        fma2(acc[r][0], x[r].x, wa0); fma2(acc[r][1], x[r].x, wa1);
        fma2(acc[r][2], x[r].x, wa2); fma2(acc[r][3], x[r].x, wa3);
        fma2(acc[r][0], x[r].y, wb0); fma2(acc[r][1], x[r].y, wb1);
        fma2(acc[r][2], x[r].y, wb2); fma2(acc[r][3], x[r].y, wb3);
    }
}

__device__ __forceinline__ void gemm8x4(ull acc[8][4],
    const float* __restrict__ sIn, const int inS, const int hin,
    const unsigned int* __restrict__ Wp, const int wld, int cq, int rbase)
{
    const float* ip = sIn + rbase * inS;
    const unsigned int* w = Wp + cq;
    uint4 ha = *(const uint4*)w;
    uint4 hb = *(const uint4*)(w + wld);
    w += 2 * wld;
    #pragma unroll 2
    for (int k = 0; k < hin - 4; k += 4) {
        uint4 nha = *(const uint4*)w;           // prefetch next quad's weights
        uint4 nhb = *(const uint4*)(w + wld);
        w += 2 * wld;
        fma_quad(acc, ip, inS, ha, hb);
        ip += 4;
        ha = nha; hb = nhb;
    }
    fma_quad(acc, ip, inS, ha, hb);             // tail quad
}

__device__ __forceinline__ void storeacc(const ull acc[8][4], float* sOut,
                                         int outS, int cq, int rbase, bool g) {
    #pragma unroll
    for (int r = 0; r < 8; r++) {
        float4 v;
        v.x = fold(acc[r][0]); v.y = fold(acc[r][1]);
        v.z = fold(acc[r][2]); v.w = fold(acc[r][3]);
        if (g) { v.x = gelu_f(v.x); v.y = gelu_f(v.y); v.z = gelu_f(v.z); v.w = gelu_f(v.w); }
        *(float4*)(sOut + (rbase + r) * outS + cq) = v;
    }
}

// ---- warp LayerNorm over 256 contiguous floats; lane owns cols lane*8..+7 ----
__device__ __forceinline__ void warp_ln(const float* __restrict__ src4,
                                        float* __restrict__ dst,
                                        const float* __restrict__ gam,
                                        const float* __restrict__ bet, int lane) {
    float4 v0 = *(const float4*)(src4 + lane * 8);
    float4 v1 = *(const float4*)(src4 + lane * 8 + 4);
    float s = v0.x + v0.y + v0.z + v0.w + v1.x + v1.y + v1.z + v1.w;
    #pragma unroll
    for (int o = 16; o; o >>= 1) s += __shfl_xor_sync(0xffffffffu, s, o);
    float mu = s * (1.f / HH);
    float q =
        (v0.x - mu) * (v0.x - mu) + (v0.y - mu) * (v0.y - mu) +
        (v0.z - mu) * (v0.z - mu) + (v0.w - mu) * (v0.w - mu) +
        (v1.x - mu) * (v1.x - mu) + (v1.y - mu) * (v1.y - mu) +
        (v1.z - mu) * (v1.z - mu) + (v1.w - mu) * (v1.w - mu);
    #pragma unroll
    for (int o = 16; o; o >>= 1) q += __shfl_xor_sync(0xffffffffu, q, o);
    float rs = rsqrtf(q * (1.f / HH) + 1e-5f);
    float4 g0 = *(const float4*)(gam + lane * 8);
    float4 g1 = *(const float4*)(gam + lane * 8 + 4);
    float4 b0 = *(const float4*)(bet + lane * 8);
    float4 b1 = *(const float4*)(bet + lane * 8 + 4);
    float4 o0, o1;
    o0.x = (v0.x - mu) * rs * g0.x + b0.x;
    o0.y = (v0.y - mu) * rs * g0.y + b0.y;
    o0.z = (v0.z - mu) * rs * g0.z + b0.z;
    o0.w = (v0.w - mu) * rs * g0.w + b0.w;
    o1.x = (v1.x - mu) * rs * g1.x + b1.x;
    o1.y = (v1.y - mu) * rs * g1.y + b1.y;
    o1.z = (v1.z - mu) * rs * g1.z + b1.z;
    o1.w = (v1.w - mu) * rs * g1.w + b1.w;
    *(float4*)(dst + lane * 8) = o0;
    *(float4*)(dst + lane * 8 + 4) = o1;
}

// ---------------- fused weight repack (fp32 -> half2 k-pairs) ----------------
__device__ __forceinline__ void rp_seg(const float* __restrict__ src,
                                       unsigned int* __restrict__ dst,
                                       int rows2, int cols) {
    int idx = blockIdx.x * blockDim.x + threadIdx.x;
    int total = rows2 * cols;
    int stride = gridDim.x * blockDim.x;
    for (; idx < total; idx += stride) {
        int r2 = idx / cols, cc = idx - r2 * cols;
        __half2 hv = __floats2half2_rn(src[(size_t)(2 * r2) * cols + cc],
                                       src[(size_t)(2 * r2 + 1) * cols + cc]);
        dst[idx] = *reinterpret_cast<unsigned int*>(&hv);
    }
}

__global__ void repack_all(
    const float* We, const float* Wn, const float* Wm, const float* Wq,
    const float* Wo, const float* w1n, const float* w2n,
    const float* w1e, const float* w2e)
{
    switch (blockIdx.y) {
        case 0: rp_seg(We,  g_wph + OFF_WE,   512, 256); break;
        case 1: rp_seg(Wn,  g_wph + OFF_WN,  2048, 256); break;
        case 2: rp_seg(Wm,  g_wph + OFF_WM,  2048, 256); break;
        case 3: rp_seg(Wq,  g_wph + OFF_WQKV,1024, 768); break;
        case 4: rp_seg(Wo,  g_wph + OFF_WO,  1024, 256); break;
        case 5: rp_seg(w1n, g_wph + OFF_W1N, 1024, 512); break;
        case 6: rp_seg(w2n, g_wph + OFF_W2N, 2048, 256); break;
        case 7: rp_seg(w1e, g_wph + OFF_W1E, 1024, 512); break;
        case 8: rp_seg(w2e, g_wph + OFF_W2E, 2048, 256); break;
    }
}

// ---------------- zero output ----------------
__global__ void zero_kernel(float4* __restrict__ p, int n4) {
    int idx = blockIdx.x * blockDim.x + threadIdx.x;
    int stride = gridDim.x * blockDim.x;
    float4 z = make_float4(0.f, 0.f, 0.f, 0.f);
    for (; idx < n4; idx += stride) p[idx] = z;
}

// ---------------- gating kernel ----------------
__global__ void gate_kernel(const float* __restrict__ nf, const float* __restrict__ wg) {
    int n = blockIdx.x;
    int tid = threadIdx.x;
    float x = nf[n * HH + tid];
    float p[NE];
    #pragma unroll
    for (int e = 0; e < NE; e++) p[e] = x * wg[tid * NE + e];
    #pragma unroll
    for (int e = 0; e < NE; e++)
        #pragma unroll
        for (int o = 16; o; o >>= 1) p[e] += __shfl_xor_sync(0xffffffffu, p[e], o);
    __shared__ float logits[NE];
    if (tid < NE) logits[tid] = 0.f;
    __syncthreads();
    if ((tid & 31) == 0) {
        #pragma unroll
        for (int e = 0; e < NE; e++) atomicAdd(&logits[e], p[e]);
    }
    __syncthreads();
    if (tid == 0) {
        float v0 = -1e30f, v1 = -1e30f; int i0 = 0, i1 = 0;
        for (int e = 0; e < NE; e++) {
            float v = logits[e];
            if (v > v0) { v1 = v0; i1 = i0; v0 = v; i0 = e; }
            else if (v > v1) { v1 = v; i1 = e; }
        }
        float e1 = __expf(v1 - v0);
        float g0 = 1.f / (1.f + e1);
        g_te[n * 2 + 0] = i0; g_te[n * 2 + 1] = i1;
        g_tg[n * 2 + 0] = g0; g_tg[n * 2 + 1] = 1.f - g0;
    }
}

// ---------------- main kernel: one CTA (256 thr) per (node, slot) ----------------
__global__ __launch_bounds__(256, 2) void moe_kernel(
    const float* __restrict__ node_features,
    const float* __restrict__ edge_features,
    const float* __restrict__ edge_raw,
    const int*   __restrict__ neighbor_list,
    const float* __restrict__ neighbor_mask,
    const float* __restrict__ attn_mask,
    const float* __restrict__ b_edge, const float* __restrict__ b_node,
    const float* __restrict__ b_msg,  const float* __restrict__ b_qkv,
    const float* __restrict__ b_out,
    const float* __restrict__ lag_, const float* __restrict__ lab_,
    const float* __restrict__ lfg_, const float* __restrict__ lfb_,
    const float* __restrict__ b1n, const float* __restrict__ b2n,
    const float* __restrict__ b1e, const float* __restrict__ b2e,
    float* __restrict__ out)
{
    extern __shared__ float sm[];
    float* sA   = sm;                 // KK*SS
    float* sB   = sA + KK * SS;
    float* sC   = sB + KK * SS;
    float* sNh  = sC + KK * SS;       // HH
    float* sVec = sNh + HH;           // HH
    float* sHn  = sVec + HH;          // FF
    float* sMsk = sHn + FF;           // KK
    float* sAm  = sMsk + KK;          // KK
    float* sRed = sAm + KK;           // 8

    const int n = blockIdx.x;
    const int slot = blockIdx.y;
    const int tid = threadIdx.x;
    const int lane = tid & 31, wid = tid >> 5;
    const int j = tid;
    const int cq = (tid & 63) * 4;     // 4 adjacent output cols
    const int rbase = (tid >> 6) * 8;  // 8 rows

    const int e = g_te[n * 2 + slot];
    const float gate = g_tg[n * 2 + slot];
    const float* lag = lag_ + e * HH;
    const float* lab = lab_ + e * HH;
    const float* lfg = lfg_ + e * HH;
    const float* lfb = lfb_ + e * HH;

    if (tid < KK) {
        sMsk[tid] = neighbor_mask[n * KK + tid];
        sAm[tid]  = attn_mask[n * KK + tid];
    }
    __syncthreads();
    float cnt = 0.f;
    #pragma unroll
    for (int k = 0; k < KK; k++) cnt += sMsk[k];
    float inv_cnt = 1.f / (cnt + 1e-5f);

    const float xj = node_features[(size_t)n * HH + j];

    // ---- recv layernorm -> sNh ----
    {
        float s = bsum256(xj, sRed);
        float mu = s * (1.f / HH);
        float d = xj - mu;
        float q = bsum256(d * d, sRed);
        float rs = rsqrtf(q * (1.f / HH) + 1e-5f);
        sNh[j] = d * rs * lag[j] + lab[j];
    }
    __syncthreads();

    // ---- edge_raw -> sA (32x128 dense) ----
    {
        const float4* src = (const float4*)(edge_raw + (size_t)n * KK * DEn);
        float4* dst = (float4*)sA;
        #pragma unroll
        for (int i = 0; i < 4; i++) dst[tid + 256 * i] = src[tid + 256 * i];
    }
    // ---- rv = recv @ Wn_bottom + bn -> sVec ----
    {
        const unsigned int* W = g_wph + OFF_WN + (size_t)e * 65536u + 128u * 256u + j;
        ull a0 = pk2(b_node[e * HH + j], 0.f);
        ull a1 = pk2(0.f, 0.f), a2 = pk2(0.f, 0.f), a3 = pk2(0.f, 0.f);
        #pragma unroll 8
        for (int i = 0; i < 128; i += 4) {
            fma2(a0, *(const ull*)(sNh + 2 * i),     h2f2(W[(size_t)i * 256]));
            fma2(a1, *(const ull*)(sNh + 2 * i + 2), h2f2(W[(size_t)(i + 1) * 256]));
            fma2(a2, *(const ull*)(sNh + 2 * i + 4), h2f2(W[(size_t)(i + 2) * 256]));
            fma2(a3, *(const ull*)(sNh + 2 * i + 6), h2f2(W[(size_t)(i + 3) * 256]));
        }
        sVec[j] = fold(a0) + fold(a1) + fold(a2) + fold(a3);
    }
    __syncthreads();

    // ---- eh = gelu(edge_raw(sA) @ We + be) -> sB ----
    {
        ull acc[8][4];
        initacc(acc, b_edge + e * HH, cq);
        gemm8x4(acc, sA, DEn, DEn, g_wph + OFF_WE + (size_t)e * 16384u, 256, cq, rbase);
        storeacc(acc, sB, SS, cq, rbase, true);
    }
    __syncthreads();

    // ---- sender = LN(node_features[nbr]) -> sA (warp per row) ----
    for (int k = wid; k < KK; k += 8) {
        int nbr = neighbor_list[n * KK + k];
        warp_ln(node_features + (size_t)nbr * HH, sA + k * SS, lag, lab, lane);
    }
    __syncthreads();

    // ---- nodeh = gelu(sender(sA)@Wn_top + rv) -> sC ----
    {
        ull acc[8][4];
        initacc(acc, sVec, cq);
        gemm8x4(acc, sA, SS, HH, g_wph + OFF_WN + (size_t)e * 65536u, 256, cq, rbase);
        storeacc(acc, sC, SS, cq, rbase, true);
    }
    __syncthreads();

    // ---- msg = gelu(eh(sB)@Wm_top + nodeh(sC)@Wm_bot + bm) -> sA ----
    {
        const unsigned int* Wt = g_wph + OFF_WM + (size_t)e * 65536u;
        ull acc[8][4];
        initacc(acc, b_msg + e * HH, cq);
        gemm8x4(acc, sB, SS, HH, Wt, 256, cq, rbase);
        gemm8x4(acc, sC, SS, HH, Wt + 128u * 256u, 256, cq, rbase);
        storeacc(acc, sA, SS, cq, rbase, true);
    }
    __syncthreads();

    // ---- qkv from msg(sA): q->sB, k->sC, v->sA (in-place after barrier) ----
    {
        const unsigned int* W = g_wph + OFF_WQKV + (size_t)e * 98304u;
        const float* bq = b_qkv + e * 3 * HH;
        {
            ull acc[8][4];
            initacc(acc, bq, cq);
            gemm8x4(acc, sA, SS, HH, W, 768, cq, rbase);
            storeacc(acc, sB, SS, cq, rbase, false);
        }
        {
            ull acc[8][4];
            initacc(acc, bq + 256, cq);
            gemm8x4(acc, sA, SS, HH, W + 256, 768, cq, rbase);
            storeacc(acc, sC, SS, cq, rbase, false);
        }
        {
            ull acc[8][4];
            initacc(acc, bq + 512, cq);
            gemm8x4(acc, sA, SS, HH, W + 512, 768, cq, rbase);
            __syncthreads();                  // all reads of msg complete
            storeacc(acc, sA, SS, cq, rbase, false);
        }
    }
    __syncthreads();

    // ---- attention (f32x2): warp = head, lane = query. q(sB), k(sC), v(sA) -> sB ----
    {
        const int h = wid;
        const int a = lane;
        const float* qp = sB + a * SS + h * DHn;
        ulonglong2 qv[8];
        #pragma unroll
        for (int i = 0; i < 8; i++) qv[i] = *(const ulonglong2*)(qp + 4 * i);
        float sc[KK];
        const float scale = 0.17677669529663687f;   // 1/sqrt(32)
        #pragma unroll
        for (int b = 0; b < KK; b++) {
            const float* kp = sC + b * SS + h * DHn;
            ull d0 = pk2(0.f, 0.f), d1 = pk2(0.f, 0.f);
            #pragma unroll
            for (int i = 0; i < 8; i++) {
                ulonglong2 kv = *(const ulonglong2*)(kp + 4 * i);
                fma2(d0, qv[i].x, kv.x);
                fma2(d1, qv[i].y, kv.y);
            }
            sc[b] = (fold(d0) + fold(d1)) * scale + sAm[b];
        }
        float m = sc[0];
        #pragma unroll
        for (int b = 1; b < KK; b++) m = fmaxf(m, sc[b]);
        float ssum = 0.f;
        #pragma unroll
        for (int b = 0; b < KK; b++) { sc[b] = __expf(sc[b] - m); ssum += sc[b]; }
        float inv = 1.f / ssum;
        ull o[16];
        #pragma unroll
        for (int i = 0; i < 16; i++) o[i] = pk2(0.f, 0.f);
        #pragma unroll
        for (int b = 0; b < KK; b++) {
            float p = sc[b] * inv;
            ull pp = pk2(p, p);
            const float* vp = sA + b * SS + h * DHn;
            #pragma unroll
            for (int i = 0; i < 8; i++) {
                ulonglong2 vv = *(const ulonglong2*)(vp + 4 * i);
                fma2(o[2 * i], pp, vv.x);
                fma2(o[2 * i + 1], pp, vv.y);
            }
        }
        __syncthreads();                      // done reading q before overwrite
        float* op = sB + a * SS + h * DHn;
        #pragma unroll
        for (int i = 0; i < 16; i++) *(ull*)(op + 2 * i) = o[i];
    }
    __syncthreads();

    // ---- edge_out = attn_out(sB) @ Wo + bo -> sC ----
    {
        ull acc[8][4];
        initacc(acc, b_out + e * HH, cq);
        gemm8x4(acc, sB, SS, HH, g_wph + OFF_WO + (size_t)e * 32768u, 256, cq, rbase);
        storeacc(acc, sC, SS, cq, rbase, false);
    }
    __syncthreads();

    // ---- masked-mean aggregate -> nfj ----
    float nfj;
    {
        float s = 0.f;
        #pragma unroll
        for (int k = 0; k < KK; k++) s += sC[k * SS + j] * sMsk[k];
        nfj = s * inv_cnt + xj;
    }
    __syncthreads();
    // ---- ef = edge_out + edge_features (RMW sC) ----
    {
        const float4* efsrc = (const float4*)(edge_features + (size_t)n * KK * HH);
        #pragma unroll
        for (int i = 0; i < 8; i++) {
            int idx = tid + 256 * i;           // float4 idx, 64 per row
            int row = idx >> 6, c4 = (idx & 63) * 4;
            float4* d4 = (float4*)(sC + row * SS + c4);
            float4 v = *d4;
            float4 a = efsrc[idx];
            v.x += a.x; v.y += a.y; v.z += a.z; v.w += a.w;
            *d4 = v;
        }
    }
    __syncthreads();

    // ---- node FFN LN -> sVec ----
    {
        float s = bsum256(nfj, sRed);
        float mu = s * (1.f / HH);
        float d = nfj - mu;
        float q = bsum256(d * d, sRed);
        float rs = rsqrtf(q * (1.f / HH) + 1e-5f);
        sVec[j] = d * rs * lfg[j] + lfb[j];
    }
    __syncthreads();
    // ---- W1n: 2 outputs per thread ----
    {
        const unsigned int* W = g_wph + OFF_W1N + (size_t)e * 65536u;
        ull a0 = pk2(b1n[e * FF + tid], 0.f), a1 = pk2(0.f, 0.f);
        ull c0 = pk2(b1n[e * FF + tid + 256], 0.f), c1 = pk2(0.f, 0.f);
        #pragma unroll 8
        for (int i = 0; i < 128; i += 2) {
            ull x0 = *(const ull*)(sVec + 2 * i);
            ull x1 = *(const ull*)(sVec + 2 * i + 2);
            fma2(a0, x0, h2f2(W[(size_t)i * 512 + tid]));
            fma2(c0, x0, h2f2(W[(size_t)i * 512 + tid + 256]));
            fma2(a1, x1, h2f2(W[(size_t)(i + 1) * 512 + tid]));
            fma2(c1, x1, h2f2(W[(size_t)(i + 1) * 512 + tid + 256]));
        }
        sHn[tid]       = gelu_f(fold(a0) + fold(a1));
        sHn[tid + 256] = gelu_f(fold(c0) + fold(c1));
    }
    __syncthreads();
    // ---- W2n -> node_final ----
    float node_final;
    {
        const unsigned int* W = g_wph + OFF_W2N + (size_t)e * 65536u + j;
        ull a0 = pk2(b2n[e * HH + j], 0.f);
        ull a1 = pk2(0.f, 0.f), a2 = pk2(0.f, 0.f), a3 = pk2(0.f, 0.f);
        #pragma unroll 8
        for (int i = 0; i < 256; i += 4) {
            fma2(a0, *(const ull*)(sHn + 2 * i),     h2f2(W[(size_t)i * 256]));
            fma2(a1, *(const ull*)(sHn + 2 * i + 2), h2f2(W[(size_t)(i + 1) * 256]));
            fma2(a2, *(const ull*)(sHn + 2 * i + 4), h2f2(W[(size_t)(i + 2) * 256]));
            fma2(a3, *(const ull*)(sHn + 2 * i + 6), h2f2(W[(size_t)(i + 3) * 256]));
        }
        node_final = nfj + fold(a0) + fold(a1) + fold(a2) + fold(a3);
    }

    // ---- edge FFN: eh2 = LN(ef(sC)) -> sA (warp per row) ----
    for (int k = wid; k < KK; k += 8) {
        warp_ln(sC + k * SS, sA + k * SS, lfg, lfb, lane);
    }
    __syncthreads();

    // ---- hidden0 = gelu(eh2(sA)@W1e[:, :256]) -> sB ----
    {
        ull acc[8][4];
        initacc(acc, b1e + e * FF, cq);
        gemm8x4(acc, sA, SS, HH, g_wph + OFF_W1E + (size_t)e * 65536u, 512, cq, rbase);
        storeacc(acc, sB, SS, cq, rbase, true);
    }
    __syncthreads();
    // ---- sC += b2e + hidden0(sB) @ W2e_top ----
    {
        ull acc[8][4];
        initacc(acc, b2e + e * HH, cq);
        gemm8x4(acc, sB, SS, HH, g_wph + OFF_W2E + (size_t)e * 65536u, 256, cq, rbase);
        #pragma unroll
        for (int r = 0; r < 8; r++) {
            float4* d4 = (float4*)(sC + (rbase + r) * SS + cq);
            float4 v = *d4;
            v.x += fold(acc[r][0]); v.y += fold(acc[r][1]);
            v.z += fold(acc[r][2]); v.w += fold(acc[r][3]);
            *d4 = v;
        }
    }
    __syncthreads();
    // ---- hidden1 = gelu(eh2(sA)@W1e[:, 256:]) -> sB ----
    {
        ull acc[8][4];
        initacc(acc, b1e + e * FF + 256, cq);
        gemm8x4(acc, sA, SS, HH, g_wph + OFF_W1E + (size_t)e * 65536u + 256, 512, cq, rbase);
        storeacc(acc, sB, SS, cq, rbase, true);
    }
    __syncthreads();
    // ---- final = sC + hidden1(sB)@W2e_bot ; atomic write ----
    {
        ull acc[8][4];
        #pragma unroll
        for (int r = 0; r < 8; r++)
            #pragma unroll
            for (int t = 0; t < 4; t++) acc[r][t] = pk2(0.f, 0.f);
        gemm8x4(acc, sB, SS, HH, g_wph + OFF_W2E + (size_t)e * 65536u + 128u * 256u,
                256, cq, rbase);
        float* eout = out + (size_t)NN * HH + (size_t)n * KK * HH;
        #pragma unroll
        for (int r = 0; r < 8; r++) {
            int row = rbase + r;
            const float* c = sC + row * SS + cq;
            float* o = eout + (size_t)row * HH + cq;
            atomicAdd(o + 0, gate * (c[0] + fold(acc[r][0])));
            atomicAdd(o + 1, gate * (c[1] + fold(acc[r][1])));
            atomicAdd(o + 2, gate * (c[2] + fold(acc[r][2])));
            atomicAdd(o + 3, gate * (c[3] + fold(acc[r][3])));
        }
    }
    atomicAdd(out + (size_t)n * HH + j, gate * node_final);
}

static constexpr int SMEM_FLOATS = 3 * KK * SS + HH + HH + FF + KK + KK + 8;
static constexpr int SMEM_BYTES  = SMEM_FLOATS * 4;

extern "C" void kernel_launch(void* const* d_in, const int* in_sizes, int n_in,
                              void* d_out, int out_size) {
    const float* node_features = (const float*)d_in[0];
    const float* edge_features = (const float*)d_in[1];
    const float* edge_raw      = (const float*)d_in[2];
    const int*   neighbor_list = (const int*)  d_in[3];
    const float* neighbor_mask = (const float*)d_in[4];
    const float* attn_mask     = (const float*)d_in[5];
    const float* w_gate        = (const float*)d_in[6];
    const float* W_edge = (const float*)d_in[7];
    const float* b_edge = (const float*)d_in[8];
    const float* W_node = (const float*)d_in[9];
    const float* b_node = (const float*)d_in[10];
    const float* W_msg  = (const float*)d_in[11];
    const float* b_msg  = (const float*)d_in[12];
    const float* W_qkv  = (const float*)d_in[13];
    const float* b_qkv  = (const float*)d_in[14];
    const float* W_out  = (const float*)d_in[15];
    const float* b_out  = (const float*)d_in[16];
    const float* lag    = (const float*)d_in[17];
    const float* lab    = (const float*)d_in[18];
    const float* lfg    = (const float*)d_in[19];
    const float* lfb    = (const float*)d_in[20];
    const float* W1n = (const float*)d_in[21];
    const float* b1n = (const float*)d_in[22];
    const float* W2n = (const float*)d_in[23];
    const float* b2n = (const float*)d_in[24];
    const float* W1e = (const float*)d_in[25];
    const float* b1e = (const float*)d_in[26];
    const float* W2e = (const float*)d_in[27];
    const float* b2e = (const float*)d_in[28];
    float* out = (float*)d_out;

    cudaFuncSetAttribute(moe_kernel, cudaFuncAttributeMaxDynamicSharedMemorySize, SMEM_BYTES);

    dim3 rg(128, 9);
    repack_all<<<rg, 256>>>(W_edge, W_node, W_msg, W_qkv, W_out, W1n, W2n, W1e, W2e);
    gate_kernel<<<NN, 256>>>(node_features, w_gate);
    zero_kernel<<<512, 256>>>((float4*)out, out_size / 4);

    dim3 grid(NN, 2);
    moe_kernel<<<grid, 256, SMEM_BYTES>>>(
        node_features, edge_features, edge_raw, neighbor_list, neighbor_mask,
        attn_mask, b_edge, b_node, b_msg, b_qkv, b_out,
        lag, lab, lfg, lfb, b1n, b2n, b1e, b2e, out);
}

// round 15
// speedup vs baseline: 3.4405x; 3.4405x over previous
#include <cuda_runtime.h>
#include <cuda_fp16.h>
#include <math.h>

#define NN 1024
#define KK 32
#define HH 256
#define DEn 128
#define NE 8
#define DHn 32
#define FF 512
#define SS 260    // fp32 tile stride (floats)
#define LDH 264   // fp16 tile stride (halfs)

typedef unsigned long long ull;
typedef unsigned int uint;

__device__ int   g_te[NN * 2];
__device__ float g_tg[NN * 2];

// prepacked fp16 weights: k-pairs (W[2i][j], W[2i+1][j]) in one half2 (uint)
#define OFF_WE   0u
#define OFF_WN   131072u
#define OFF_WM   655360u
#define OFF_WQKV 1179648u
#define OFF_WO   1966080u
#define OFF_W1N  2228224u
#define OFF_W2N  2752512u
#define OFF_W1E  3276800u
#define OFF_W2E  3801088u
#define WP_TOTAL 4325376u
__device__ uint g_wph[WP_TOTAL];

__device__ __forceinline__ float gelu_f(float x) {
    float u = 0.7978845608028654f * (x + 0.044715f * x * x * x);
    float e = __expf(2.f * u);
    float t = 1.f - __fdividef(2.f, e + 1.f);
    return 0.5f * x * (1.f + t);
}
__device__ __forceinline__ ull pk2(float lo, float hi) {
    ull r; asm("mov.b64 %0,{%1,%2};" : "=l"(r) : "f"(lo), "f"(hi)); return r;
}
__device__ __forceinline__ void upk2(ull v, float& lo, float& hi) {
    asm("mov.b64 {%0,%1},%2;" : "=f"(lo), "=f"(hi) : "l"(v));
}
__device__ __forceinline__ void fma2(ull& d, ull a, ull b) {
    asm("fma.rn.f32x2 %0,%1,%2,%0;" : "+l"(d) : "l"(a), "l"(b));
}
__device__ __forceinline__ float fold(ull v) {
    float lo, hi; upk2(v, lo, hi); return lo + hi;
}
__device__ __forceinline__ ull h2f2(uint h) {
    __half2 hh = *reinterpret_cast<const __half2*>(&h);
    float2 f = __half22float2(hh);
    return pk2(f.x, f.y);
}
__device__ __forceinline__ uint f2h2(float a, float b) {
    __half2 hv = __floats2half2_rn(a, b);
    return *reinterpret_cast<uint*>(&hv);
}

__device__ __forceinline__ float bsum256(float v, float* red) {
    #pragma unroll
    for (int o = 16; o; o >>= 1) v += __shfl_xor_sync(0xffffffffu, v, o);
    int tid = threadIdx.x;
    if ((tid & 31) == 0) red[tid >> 5] = v;
    __syncthreads();
    float s = red[0] + red[1] + red[2] + red[3] + red[4] + red[5] + red[6] + red[7];
    __syncthreads();
    return s;
}

// ================= tensor-core warp GEMM =================
// warp covers rows 0..31 x cols [n0, n0+32). acc[m][j][4]:
// m16n8k16 D frag: c0=(g,2t) c1=(g,2t+1) c2=(g+8,2t) c3=(g+8,2t+1)
__device__ __forceinline__ void mma16816(float d[4],
    uint a0, uint a1, uint a2, uint a3, uint b0, uint b1)
{
    asm volatile(
        "mma.sync.aligned.m16n8k16.row.col.f32.f16.f16.f32 "
        "{%0,%1,%2,%3}, {%4,%5,%6,%7}, {%8,%9}, {%0,%1,%2,%3};"
        : "+f"(d[0]), "+f"(d[1]), "+f"(d[2]), "+f"(d[3])
        : "r"(a0), "r"(a1), "r"(a2), "r"(a3), "r"(b0), "r"(b1));
}

__device__ __forceinline__ void initacc(float acc[2][4][4], const float* bias,
                                        int n0, int t) {
    #pragma unroll
    for (int j = 0; j < 4; j++) {
        float b0 = bias[n0 + 8 * j + 2 * t];
        float b1 = bias[n0 + 8 * j + 2 * t + 1];
        #pragma unroll
        for (int m = 0; m < 2; m++) {
            acc[m][j][0] = b0; acc[m][j][1] = b1;
            acc[m][j][2] = b0; acc[m][j][3] = b1;
        }
    }
}
__device__ __forceinline__ void zeroacc(float acc[2][4][4]) {
    #pragma unroll
    for (int m = 0; m < 2; m++)
        #pragma unroll
        for (int j = 0; j < 4; j++)
            #pragma unroll
            for (int c = 0; c < 4; c++) acc[m][j][c] = 0.f;
}

__device__ __forceinline__ void mma_gemm(float acc[2][4][4],
    const __half* __restrict__ hIn, const int kdim,
    const uint* __restrict__ Wp, const int wld, int n0, int g, int t)
{
    const int nk = kdim >> 4;
    #pragma unroll 2
    for (int kk = 0; kk < nk; kk++) {
        uint a[2][4];
        #pragma unroll
        for (int m = 0; m < 2; m++) {
            const __half* p0 = hIn + (16 * m + g) * LDH + 16 * kk + 2 * t;
            a[m][0] = *(const uint*)(p0);
            a[m][1] = *(const uint*)(p0 + 8 * LDH);
            a[m][2] = *(const uint*)(p0 + 8);
            a[m][3] = *(const uint*)(p0 + 8 * LDH + 8);
        }
        const uint* wb = Wp + (size_t)(8 * kk + t) * wld + n0 + g;
        const uint* wb2 = wb + (size_t)4 * wld;
        #pragma unroll
        for (int j = 0; j < 4; j++) {
            uint b0 = wb[8 * j];
            uint b1 = wb2[8 * j];
            mma16816(acc[0][j], a[0][0], a[0][1], a[0][2], a[0][3], b0, b1);
            mma16816(acc[1][j], a[1][0], a[1][1], a[1][2], a[1][3], b0, b1);
        }
    }
}

__device__ __forceinline__ void storeacc_h(const float acc[2][4][4],
    __half* hOut, int n0, int g, int t, bool doGelu)
{
    #pragma unroll
    for (int m = 0; m < 2; m++) {
        int r0 = 16 * m + g;
        #pragma unroll
        for (int j = 0; j < 4; j++) {
            int c = n0 + 8 * j + 2 * t;
            float v0 = acc[m][j][0], v1 = acc[m][j][1];
            float v2 = acc[m][j][2], v3 = acc[m][j][3];
            if (doGelu) { v0 = gelu_f(v0); v1 = gelu_f(v1); v2 = gelu_f(v2); v3 = gelu_f(v3); }
            *(uint*)(hOut + r0 * LDH + c) = f2h2(v0, v1);
            *(uint*)(hOut + (r0 + 8) * LDH + c) = f2h2(v2, v3);
        }
    }
}

__device__ __forceinline__ void storeacc_f(const float acc[2][4][4],
    float* fOut, int n0, int g, int t)
{
    #pragma unroll
    for (int m = 0; m < 2; m++) {
        int r0 = 16 * m + g;
        #pragma unroll
        for (int j = 0; j < 4; j++) {
            int c = n0 + 8 * j + 2 * t;
            *(float2*)(fOut + r0 * SS + c) = make_float2(acc[m][j][0], acc[m][j][1]);
            *(float2*)(fOut + (r0 + 8) * SS + c) = make_float2(acc[m][j][2], acc[m][j][3]);
        }
    }
}

__device__ __forceinline__ void addacc_f(const float acc[2][4][4],
    float* fOut, int n0, int g, int t)
{
    #pragma unroll
    for (int m = 0; m < 2; m++) {
        int r0 = 16 * m + g;
        #pragma unroll
        for (int j = 0; j < 4; j++) {
            int c = n0 + 8 * j + 2 * t;
            float2* p0 = (float2*)(fOut + r0 * SS + c);
            float2* p1 = (float2*)(fOut + (r0 + 8) * SS + c);
            float2 u0 = *p0, u1 = *p1;
            u0.x += acc[m][j][0]; u0.y += acc[m][j][1];
            u1.x += acc[m][j][2]; u1.y += acc[m][j][3];
            *p0 = u0; *p1 = u1;
        }
    }
}

// ---- warp LayerNorm over 256 floats -> fp16 dst; lane owns cols lane*8..+7 ----
template <typename SRC>
__device__ __forceinline__ void warp_ln_h(const SRC* __restrict__ src,
                                          __half* __restrict__ dst,
                                          const float* __restrict__ gam,
                                          const float* __restrict__ bet, int lane) {
    float v[8];
    #pragma unroll
    for (int i = 0; i < 8; i++) v[i] = (float)src[lane * 8 + i];
    float s = 0.f;
    #pragma unroll
    for (int i = 0; i < 8; i++) s += v[i];
    #pragma unroll
    for (int o = 16; o; o >>= 1) s += __shfl_xor_sync(0xffffffffu, s, o);
    float mu = s * (1.f / HH);
    float q = 0.f;
    #pragma unroll
    for (int i = 0; i < 8; i++) { float d = v[i] - mu; q += d * d; }
    #pragma unroll
    for (int o = 16; o; o >>= 1) q += __shfl_xor_sync(0xffffffffu, q, o);
    float rs = rsqrtf(q * (1.f / HH) + 1e-5f);
    uint4 pack;
    float o0 = (v[0] - mu) * rs * gam[lane * 8 + 0] + bet[lane * 8 + 0];
    float o1 = (v[1] - mu) * rs * gam[lane * 8 + 1] + bet[lane * 8 + 1];
    float o2 = (v[2] - mu) * rs * gam[lane * 8 + 2] + bet[lane * 8 + 2];
    float o3 = (v[3] - mu) * rs * gam[lane * 8 + 3] + bet[lane * 8 + 3];
    float o4 = (v[4] - mu) * rs * gam[lane * 8 + 4] + bet[lane * 8 + 4];
    float o5 = (v[5] - mu) * rs * gam[lane * 8 + 5] + bet[lane * 8 + 5];
    float o6 = (v[6] - mu) * rs * gam[lane * 8 + 6] + bet[lane * 8 + 6];
    float o7 = (v[7] - mu) * rs * gam[lane * 8 + 7] + bet[lane * 8 + 7];
    pack.x = f2h2(o0, o1); pack.y = f2h2(o2, o3);
    pack.z = f2h2(o4, o5); pack.w = f2h2(o6, o7);
    *(uint4*)(dst + lane * 8) = pack;
}

// ---------------- fused weight repack (fp32 -> half2 k-pairs) ----------------
__device__ __forceinline__ void rp_seg(const float* __restrict__ src,
                                       uint* __restrict__ dst, int rows2, int cols) {
    int idx = blockIdx.x * blockDim.x + threadIdx.x;
    int total = rows2 * cols;
    int stride = gridDim.x * blockDim.x;
    for (; idx < total; idx += stride) {
        int r2 = idx / cols, cc = idx - r2 * cols;
        dst[idx] = f2h2(src[(size_t)(2 * r2) * cols + cc],
                        src[(size_t)(2 * r2 + 1) * cols + cc]);
    }
}

__global__ void repack_all(
    const float* We, const float* Wn, const float* Wm, const float* Wq,
    const float* Wo, const float* w1n, const float* w2n,
    const float* w1e, const float* w2e)
{
    switch (blockIdx.y) {
        case 0: rp_seg(We,  g_wph + OFF_WE,   512, 256); break;
        case 1: rp_seg(Wn,  g_wph + OFF_WN,  2048, 256); break;
        case 2: rp_seg(Wm,  g_wph + OFF_WM,  2048, 256); break;
        case 3: rp_seg(Wq,  g_wph + OFF_WQKV,1024, 768); break;
        case 4: rp_seg(Wo,  g_wph + OFF_WO,  1024, 256); break;
        case 5: rp_seg(w1n, g_wph + OFF_W1N, 1024, 512); break;
        case 6: rp_seg(w2n, g_wph + OFF_W2N, 2048, 256); break;
        case 7: rp_seg(w1e, g_wph + OFF_W1E, 1024, 512); break;
        case 8: rp_seg(w2e, g_wph + OFF_W2E, 2048, 256); break;
    }
}

// ---------------- zero output ----------------
__global__ void zero_kernel(float4* __restrict__ p, int n4) {
    int idx = blockIdx.x * blockDim.x + threadIdx.x;
    int stride = gridDim.x * blockDim.x;
    float4 z = make_float4(0.f, 0.f, 0.f, 0.f);
    for (; idx < n4; idx += stride) p[idx] = z;
}

// ---------------- gating kernel ----------------
__global__ void gate_kernel(const float* __restrict__ nf, const float* __restrict__ wg) {
    int n = blockIdx.x;
    int tid = threadIdx.x;
    float x = nf[n * HH + tid];
    float p[NE];
    #pragma unroll
    for (int e = 0; e < NE; e++) p[e] = x * wg[tid * NE + e];
    #pragma unroll
    for (int e = 0; e < NE; e++)
        #pragma unroll
        for (int o = 16; o; o >>= 1) p[e] += __shfl_xor_sync(0xffffffffu, p[e], o);
    __shared__ float logits[NE];
    if (tid < NE) logits[tid] = 0.f;
    __syncthreads();
    if ((tid & 31) == 0) {
        #pragma unroll
        for (int e = 0; e < NE; e++) atomicAdd(&logits[e], p[e]);
    }
    __syncthreads();
    if (tid == 0) {
        float v0 = -1e30f, v1 = -1e30f; int i0 = 0, i1 = 0;
        for (int e = 0; e < NE; e++) {
            float v = logits[e];
            if (v > v0) { v1 = v0; i1 = i0; v0 = v; i0 = e; }
            else if (v > v1) { v1 = v; i1 = e; }
        }
        float e1 = __expf(v1 - v0);
        float g0 = 1.f / (1.f + e1);
        g_te[n * 2 + 0] = i0; g_te[n * 2 + 1] = i1;
        g_tg[n * 2 + 0] = g0; g_tg[n * 2 + 1] = 1.f - g0;
    }
}

// ---------------- main kernel: one CTA (256 thr) per (node, slot) ----------------
__global__ __launch_bounds__(256, 2) void moe_kernel(
    const float* __restrict__ node_features,
    const float* __restrict__ edge_features,
    const float* __restrict__ edge_raw,
    const int*   __restrict__ neighbor_list,
    const float* __restrict__ neighbor_mask,
    const float* __restrict__ attn_mask,
    const float* __restrict__ b_edge, const float* __restrict__ b_node,
    const float* __restrict__ b_msg,  const float* __restrict__ b_qkv,
    const float* __restrict__ b_out,
    const float* __restrict__ lag_, const float* __restrict__ lab_,
    const float* __restrict__ lfg_, const float* __restrict__ lfb_,
    const float* __restrict__ b1n, const float* __restrict__ b2n,
    const float* __restrict__ b1e, const float* __restrict__ b2e,
    float* __restrict__ out)
{
    extern __shared__ float sm[];
    float* fC   = sm;                          // KK*SS fp32 tile
    float* sNh  = fC + KK * SS;                // HH
    float* sVec = sNh + HH;                    // HH
    float* sHn  = sVec + HH;                   // FF
    float* sMsk = sHn + FF;                    // KK
    float* sAm  = sMsk + KK;                   // KK
    float* sRed = sAm + KK;                    // 8
    __half* hA = (__half*)(sRed + 8);          // KK*LDH halfs
    __half* hB = hA + KK * LDH;
    __half* hC = hB + KK * LDH;

    const int n = blockIdx.x;
    const int slot = blockIdx.y;
    const int tid = threadIdx.x;
    const int lane = tid & 31, wid = tid >> 5;
    const int j = tid;
    const int g = lane >> 2, t = lane & 3;     // mma fragment coords
    const int n0 = wid * 32;                   // warp col range

    const int e = g_te[n * 2 + slot];
    const float gate = g_tg[n * 2 + slot];
    const float* lag = lag_ + e * HH;
    const float* lab = lab_ + e * HH;
    const float* lfg = lfg_ + e * HH;
    const float* lfb = lfb_ + e * HH;

    if (tid < KK) {
        sMsk[tid] = neighbor_mask[n * KK + tid];
        sAm[tid]  = attn_mask[n * KK + tid];
    }
    __syncthreads();
    float cnt = 0.f;
    #pragma unroll
    for (int k = 0; k < KK; k++) cnt += sMsk[k];
    float inv_cnt = 1.f / (cnt + 1e-5f);

    const float xj = node_features[(size_t)n * HH + j];

    // ---- recv layernorm -> sNh (fp32) ----
    {
        float s = bsum256(xj, sRed);
        float mu = s * (1.f / HH);
        float d = xj - mu;
        float q = bsum256(d * d, sRed);
        float rs = rsqrtf(q * (1.f / HH) + 1e-5f);
        sNh[j] = d * rs * lag[j] + lab[j];
    }
    __syncthreads();

    // ---- edge_raw -> hA (32x128 fp16) ----
    {
        const float4* src = (const float4*)(edge_raw + (size_t)n * KK * DEn);
        #pragma unroll
        for (int i = 0; i < 4; i++) {
            int idx = tid + 256 * i;          // float4 idx; 32 per row
            float4 v = src[idx];
            int row = idx >> 5, c4 = (idx & 31) * 4;
            uint2 h; h.x = f2h2(v.x, v.y); h.y = f2h2(v.z, v.w);
            *(uint2*)(hA + row * LDH + c4) = h;
        }
    }
    // ---- rv = recv @ Wn_bottom + bn -> sVec (GEMV, fp16 weights) ----
    {
        const uint* W = g_wph + OFF_WN + (size_t)e * 65536u + 128u * 256u + j;
        ull a0 = pk2(b_node[e * HH + j], 0.f);
        ull a1 = pk2(0.f, 0.f), a2 = pk2(0.f, 0.f), a3 = pk2(0.f, 0.f);
        #pragma unroll 8
        for (int i = 0; i < 128; i += 4) {
            fma2(a0, *(const ull*)(sNh + 2 * i),     h2f2(W[(size_t)i * 256]));
            fma2(a1, *(const ull*)(sNh + 2 * i + 2), h2f2(W[(size_t)(i + 1) * 256]));
            fma2(a2, *(const ull*)(sNh + 2 * i + 4), h2f2(W[(size_t)(i + 2) * 256]));
            fma2(a3, *(const ull*)(sNh + 2 * i + 6), h2f2(W[(size_t)(i + 3) * 256]));
        }
        sVec[j] = fold(a0) + fold(a1) + fold(a2) + fold(a3);
    }
    __syncthreads();

    // ---- eh = gelu(edge_raw(hA) @ We + be) -> hB ----
    {
        float acc[2][4][4];
        initacc(acc, b_edge + e * HH, n0, t);
        mma_gemm(acc, hA, DEn, g_wph + OFF_WE + (size_t)e * 16384u, 256, n0, g, t);
        storeacc_h(acc, hB, n0, g, t, true);
    }
    __syncthreads();

    // ---- sender = LN(node_features[nbr]) -> hA ----
    for (int k = wid; k < KK; k += 8) {
        int nbr = neighbor_list[n * KK + k];
        warp_ln_h(node_features + (size_t)nbr * HH, hA + k * LDH, lag, lab, lane);
    }
    __syncthreads();

    // ---- nodeh = gelu(sender(hA)@Wn_top + rv) -> hC ----
    {
        float acc[2][4][4];
        initacc(acc, sVec, n0, t);
        mma_gemm(acc, hA, HH, g_wph + OFF_WN + (size_t)e * 65536u, 256, n0, g, t);
        storeacc_h(acc, hC, n0, g, t, true);
    }
    __syncthreads();

    // ---- msg = gelu(eh(hB)@Wm_top + nodeh(hC)@Wm_bot + bm) -> hA ----
    {
        const uint* Wt = g_wph + OFF_WM + (size_t)e * 65536u;
        float acc[2][4][4];
        initacc(acc, b_msg + e * HH, n0, t);
        mma_gemm(acc, hB, HH, Wt, 256, n0, g, t);
        mma_gemm(acc, hC, HH, Wt + 128u * 256u, 256, n0, g, t);
        storeacc_h(acc, hA, n0, g, t, true);
    }
    __syncthreads();

    // ---- qkv from msg(hA): q->hB, k->hC, v->hA (in-place after barrier) ----
    {
        const uint* W = g_wph + OFF_WQKV + (size_t)e * 98304u;
        const float* bq = b_qkv + e * 3 * HH;
        {
            float acc[2][4][4];
            initacc(acc, bq, n0, t);
            mma_gemm(acc, hA, HH, W, 768, n0, g, t);
            storeacc_h(acc, hB, n0, g, t, false);
        }
        {
            float acc[2][4][4];
            initacc(acc, bq + 256, n0, t);
            mma_gemm(acc, hA, HH, W + 256, 768, n0, g, t);
            storeacc_h(acc, hC, n0, g, t, false);
        }
        {
            float acc[2][4][4];
            initacc(acc, bq + 512, n0, t);
            mma_gemm(acc, hA, HH, W + 512, 768, n0, g, t);
            __syncthreads();                  // all reads of msg complete
            storeacc_h(acc, hA, n0, g, t, false);
        }
    }
    __syncthreads();

    // ---- attention: warp = head, lane = query. q(hB), k(hC), v(hA) -> hB in place ----
    {
        const int h = wid;
        const int a = lane;
        const __half* qp = hB + a * LDH + h * DHn;
        ull qv[16];
        #pragma unroll
        for (int i = 0; i < 4; i++) {
            uint4 u = *(const uint4*)(qp + 8 * i);
            qv[4 * i + 0] = h2f2(u.x); qv[4 * i + 1] = h2f2(u.y);
            qv[4 * i + 2] = h2f2(u.z); qv[4 * i + 3] = h2f2(u.w);
        }
        float sc[KK];
        const float scale = 0.17677669529663687f;   // 1/sqrt(32)
        #pragma unroll
        for (int b = 0; b < KK; b++) {
            const __half* kp = hC + b * LDH + h * DHn;
            ull d0 = pk2(0.f, 0.f), d1 = pk2(0.f, 0.f);
            #pragma unroll
            for (int i = 0; i < 4; i++) {
                uint4 u = *(const uint4*)(kp + 8 * i);
                fma2(d0, qv[4 * i + 0], h2f2(u.x));
                fma2(d1, qv[4 * i + 1], h2f2(u.y));
                fma2(d0, qv[4 * i + 2], h2f2(u.z));
                fma2(d1, qv[4 * i + 3], h2f2(u.w));
            }
            sc[b] = (fold(d0) + fold(d1)) * scale + sAm[b];
        }
        float m = sc[0];
        #pragma unroll
        for (int b = 1; b < KK; b++) m = fmaxf(m, sc[b]);
        float ssum = 0.f;
        #pragma unroll
        for (int b = 0; b < KK; b++) { sc[b] = __expf(sc[b] - m); ssum += sc[b]; }
        float inv = 1.f / ssum;
        ull o[16];
        #pragma unroll
        for (int i = 0; i < 16; i++) o[i] = pk2(0.f, 0.f);
        #pragma unroll
        for (int b = 0; b < KK; b++) {
            float p = sc[b] * inv;
            ull pp = pk2(p, p);
            const __half* vp = hA + b * LDH + h * DHn;
            #pragma unroll
            for (int i = 0; i < 4; i++) {
                uint4 u = *(const uint4*)(vp + 8 * i);
                fma2(o[4 * i + 0], pp, h2f2(u.x));
                fma2(o[4 * i + 1], pp, h2f2(u.y));
                fma2(o[4 * i + 2], pp, h2f2(u.z));
                fma2(o[4 * i + 3], pp, h2f2(u.w));
            }
        }
        // in-place store over q row (only this lane reads it)
        __half* op = hB + a * LDH + h * DHn;
        #pragma unroll
        for (int i = 0; i < 16; i++) {
            float lo, hi; upk2(o[i], lo, hi);
            *(uint*)(op + 2 * i) = f2h2(lo, hi);
        }
    }
    __syncthreads();

    // ---- edge_out = attn_out(hB) @ Wo + bo -> fC (fp32) ----
    {
        float acc[2][4][4];
        initacc(acc, b_out + e * HH, n0, t);
        mma_gemm(acc, hB, HH, g_wph + OFF_WO + (size_t)e * 32768u, 256, n0, g, t);
        storeacc_f(acc, fC, n0, g, t);
    }
    __syncthreads();

    // ---- masked-mean aggregate -> nfj ----
    float nfj;
    {
        float s = 0.f;
        #pragma unroll
        for (int k = 0; k < KK; k++) s += fC[k * SS + j] * sMsk[k];
        nfj = s * inv_cnt + xj;
    }
    __syncthreads();
    // ---- ef = edge_out + edge_features (RMW fC) ----
    {
        const float4* efsrc = (const float4*)(edge_features + (size_t)n * KK * HH);
        #pragma unroll
        for (int i = 0; i < 8; i++) {
            int idx = tid + 256 * i;           // float4 idx, 64 per row
            int row = idx >> 6, c4 = (idx & 63) * 4;
            float4* d4 = (float4*)(fC + row * SS + c4);
            float4 v = *d4;
            float4 a = efsrc[idx];
            v.x += a.x; v.y += a.y; v.z += a.z; v.w += a.w;
            *d4 = v;
        }
    }
    __syncthreads();

    // ---- node FFN LN -> sVec ----
    {
        float s = bsum256(nfj, sRed);
        float mu = s * (1.f / HH);
        float d = nfj - mu;
        float q = bsum256(d * d, sRed);
        float rs = rsqrtf(q * (1.f / HH) + 1e-5f);
        sVec[j] = d * rs * lfg[j] + lfb[j];
    }
    __syncthreads();
    // ---- W1n GEMV: 2 outputs per thread ----
    {
        const uint* W = g_wph + OFF_W1N + (size_t)e * 65536u;
        ull a0 = pk2(b1n[e * FF + tid], 0.f), a1 = pk2(0.f, 0.f);
        ull c0 = pk2(b1n[e * FF + tid + 256], 0.f), c1 = pk2(0.f, 0.f);
        #pragma unroll 8
        for (int i = 0; i < 128; i += 2) {
            ull x0 = *(const ull*)(sVec + 2 * i);
            ull x1 = *(const ull*)(sVec + 2 * i + 2);
            fma2(a0, x0, h2f2(W[(size_t)i * 512 + tid]));
            fma2(c0, x0, h2f2(W[(size_t)i * 512 + tid + 256]));
            fma2(a1, x1, h2f2(W[(size_t)(i + 1) * 512 + tid]));
            fma2(c1, x1, h2f2(W[(size_t)(i + 1) * 512 + tid + 256]));
        }
        sHn[tid]       = gelu_f(fold(a0) + fold(a1));
        sHn[tid + 256] = gelu_f(fold(c0) + fold(c1));
    }
    __syncthreads();
    // ---- W2n GEMV -> node_final ----
    float node_final;
    {
        const uint* W = g_wph + OFF_W2N + (size_t)e * 65536u + j;
        ull a0 = pk2(b2n[e * HH + j], 0.f);
        ull a1 = pk2(0.f, 0.f), a2 = pk2(0.f, 0.f), a3 = pk2(0.f, 0.f);
        #pragma unroll 8
        for (int i = 0; i < 256; i += 4) {
            fma2(a0, *(const ull*)(sHn + 2 * i),     h2f2(W[(size_t)i * 256]));
            fma2(a1, *(const ull*)(sHn + 2 * i + 2), h2f2(W[(size_t)(i + 1) * 256]));
            fma2(a2, *(const ull*)(sHn + 2 * i + 4), h2f2(W[(size_t)(i + 2) * 256]));
            fma2(a3, *(const ull*)(sHn + 2 * i + 6), h2f2(W[(size_t)(i + 3) * 256]));
        }
        node_final = nfj + fold(a0) + fold(a1) + fold(a2) + fold(a3);
    }

    // ---- edge FFN: eh2 = LN(ef(fC)) -> hA ----
    for (int k = wid; k < KK; k += 8) {
        warp_ln_h(fC + k * SS, hA + k * LDH, lfg, lfb, lane);
    }
    __syncthreads();

    // ---- hidden0 = gelu(eh2(hA)@W1e[:, :256]) -> hB ----
    {
        float acc[2][4][4];
        initacc(acc, b1e + e * FF, n0, t);
        mma_gemm(acc, hA, HH, g_wph + OFF_W1E + (size_t)e * 65536u, 512, n0, g, t);
        storeacc_h(acc, hB, n0, g, t, true);
    }
    __syncthreads();
    // ---- fC += b2e + hidden0(hB) @ W2e_top ----
    {
        float acc[2][4][4];
        initacc(acc, b2e + e * HH, n0, t);
        mma_gemm(acc, hB, HH, g_wph + OFF_W2E + (size_t)e * 65536u, 256, n0, g, t);
        addacc_f(acc, fC, n0, g, t);
    }
    __syncthreads();
    // ---- hidden1 = gelu(eh2(hA)@W1e[:, 256:]) -> hB ----
    {
        float acc[2][4][4];
        initacc(acc, b1e + e * FF + 256, n0, t);
        mma_gemm(acc, hA, HH, g_wph + OFF_W1E + (size_t)e * 65536u + 256, 512, n0, g, t);
        storeacc_h(acc, hB, n0, g, t, true);
    }
    __syncthreads();
    // ---- final = fC + hidden1(hB)@W2e_bot ; atomic write ----
    {
        float acc[2][4][4];
        zeroacc(acc);
        mma_gemm(acc, hB, HH, g_wph + OFF_W2E + (size_t)e * 65536u + 128u * 256u,
                 256, n0, g, t);
        float* eout = out + (size_t)NN * HH + (size_t)n * KK * HH;
        #pragma unroll
        for (int m = 0; m < 2; m++) {
            #pragma unroll
            for (int jj = 0; jj < 4; jj++) {
                int c = n0 + 8 * jj + 2 * t;
                int r0 = 16 * m + g, r1 = r0 + 8;
                atomicAdd(eout + (size_t)r0 * HH + c,
                          gate * (fC[r0 * SS + c] + acc[m][jj][0]));
                atomicAdd(eout + (size_t)r0 * HH + c + 1,
                          gate * (fC[r0 * SS + c + 1] + acc[m][jj][1]));
                atomicAdd(eout + (size_t)r1 * HH + c,
                          gate * (fC[r1 * SS + c] + acc[m][jj][2]));
                atomicAdd(eout + (size_t)r1 * HH + c + 1,
                          gate * (fC[r1 * SS + c + 1] + acc[m][jj][3]));
            }
        }
    }
    atomicAdd(out + (size_t)n * HH + j, gate * node_final);
}

static constexpr int SMEM_BYTES =
    (KK * SS + HH + HH + FF + KK + KK + 8) * 4 + 3 * KK * LDH * 2;

extern "C" void kernel_launch(void* const* d_in, const int* in_sizes, int n_in,
                              void* d_out, int out_size) {
    const float* node_features = (const float*)d_in[0];
    const float* edge_features = (const float*)d_in[1];
    const float* edge_raw      = (const float*)d_in[2];
    const int*   neighbor_list = (const int*)  d_in[3];
    const float* neighbor_mask = (const float*)d_in[4];
    const float* attn_mask     = (const float*)d_in[5];
    const float* w_gate        = (const float*)d_in[6];
    const float* W_edge = (const float*)d_in[7];
    const float* b_edge = (const float*)d_in[8];
    const float* W_node = (const float*)d_in[9];
    const float* b_node = (const float*)d_in[10];
    const float* W_msg  = (const float*)d_in[11];
    const float* b_msg  = (const float*)d_in[12];
    const float* W_qkv  = (const float*)d_in[13];
    const float* b_qkv  = (const float*)d_in[14];
    const float* W_out  = (const float*)d_in[15];
    const float* b_out  = (const float*)d_in[16];
    const float* lag    = (const float*)d_in[17];
    const float* lab    = (const float*)d_in[18];
    const float* lfg    = (const float*)d_in[19];
    const float* lfb    = (const float*)d_in[20];
    const float* W1n = (const float*)d_in[21];
    const float* b1n = (const float*)d_in[22];
    const float* W2n = (const float*)d_in[23];
    const float* b2n = (const float*)d_in[24];
    const float* W1e = (const float*)d_in[25];
    const float* b1e = (const float*)d_in[26];
    const float* W2e = (const float*)d_in[27];
    const float* b2e = (const float*)d_in[28];
    float* out = (float*)d_out;

    cudaFuncSetAttribute(moe_kernel, cudaFuncAttributeMaxDynamicSharedMemorySize, SMEM_BYTES);

    dim3 rg(128, 9);
    repack_all<<<rg, 256>>>(W_edge, W_node, W_msg, W_qkv, W_out, W1n, W2n, W1e, W2e);
    gate_kernel<<<NN, 256>>>(node_features, w_gate);
    zero_kernel<<<512, 256>>>((float4*)out, out_size / 4);

    dim3 grid(NN, 2);
    moe_kernel<<<grid, 256, SMEM_BYTES>>>(
        node_features, edge_features, edge_raw, neighbor_list, neighbor_mask,
        attn_mask, b_edge, b_node, b_msg, b_qkv, b_out,
        lag, lab, lfg, lfb, b1n, b2n, b1e, b2e, out);
}

// round 16
// speedup vs baseline: 3.4751x; 1.0101x over previous
#include <cuda_runtime.h>
#include <cuda_fp16.h>
#include <math.h>

#define NN 1024
#define KK 32
#define HH 256
#define DEn 128
#define NE 8
#define DHn 32
#define FF 512
#define SS 260    // fp32 tile stride (floats)
#define LDH 264   // fp16 tile stride (halfs)

typedef unsigned long long ull;
typedef unsigned int uint;

__device__ int   g_te[NN * 2];
__device__ float g_tg[NN * 2];

// fp16 weights, k-pair-major with fragment-permuted columns:
// idx = kp*N + colp,  colp = (col&~31) + (col&7)*4 + ((col&31)>>3)
#define OFF_WE   0u
#define OFF_WN   131072u
#define OFF_WM   655360u
#define OFF_WQKV 1179648u
#define OFF_WO   1966080u
#define OFF_W1N  2228224u
#define OFF_W2N  2752512u
#define OFF_W1E  3276800u
#define OFF_W2E  3801088u
#define WP_TOTAL 4325376u
__device__ uint g_wph[WP_TOTAL];

__device__ __forceinline__ int cperm(int col) {
    return (col & ~31) + (col & 7) * 4 + ((col & 31) >> 3);
}

__device__ __forceinline__ float gelu_f(float x) {
    float u = 0.7978845608028654f * (x + 0.044715f * x * x * x);
    float e = __expf(2.f * u);
    float t = 1.f - __fdividef(2.f, e + 1.f);
    return 0.5f * x * (1.f + t);
}
__device__ __forceinline__ ull pk2(float lo, float hi) {
    ull r; asm("mov.b64 %0,{%1,%2};" : "=l"(r) : "f"(lo), "f"(hi)); return r;
}
__device__ __forceinline__ void upk2(ull v, float& lo, float& hi) {
    asm("mov.b64 {%0,%1},%2;" : "=f"(lo), "=f"(hi) : "l"(v));
}
__device__ __forceinline__ void fma2(ull& d, ull a, ull b) {
    asm("fma.rn.f32x2 %0,%1,%2,%0;" : "+l"(d) : "l"(a), "l"(b));
}
__device__ __forceinline__ float fold(ull v) {
    float lo, hi; upk2(v, lo, hi); return lo + hi;
}
__device__ __forceinline__ ull h2f2(uint h) {
    __half2 hh = *reinterpret_cast<const __half2*>(&h);
    float2 f = __half22float2(hh);
    return pk2(f.x, f.y);
}
__device__ __forceinline__ uint f2h2(float a, float b) {
    __half2 hv = __floats2half2_rn(a, b);
    return *reinterpret_cast<uint*>(&hv);
}

__device__ __forceinline__ float bsum256(float v, float* red) {
    #pragma unroll
    for (int o = 16; o; o >>= 1) v += __shfl_xor_sync(0xffffffffu, v, o);
    int tid = threadIdx.x;
    if ((tid & 31) == 0) red[tid >> 5] = v;
    __syncthreads();
    float s = red[0] + red[1] + red[2] + red[3] + red[4] + red[5] + red[6] + red[7];
    __syncthreads();
    return s;
}

// ================= tensor-core warp GEMM =================
__device__ __forceinline__ void mma16816(float d[4],
    uint a0, uint a1, uint a2, uint a3, uint b0, uint b1)
{
    asm volatile(
        "mma.sync.aligned.m16n8k16.row.col.f32.f16.f16.f32 "
        "{%0,%1,%2,%3}, {%4,%5,%6,%7}, {%8,%9}, {%0,%1,%2,%3};"
        : "+f"(d[0]), "+f"(d[1]), "+f"(d[2]), "+f"(d[3])
        : "r"(a0), "r"(a1), "r"(a2), "r"(a3), "r"(b0), "r"(b1));
}

__device__ __forceinline__ void ldsm4(uint a[4], const __half* p) {
    uint addr = (uint)__cvta_generic_to_shared(p);
    asm volatile("ldmatrix.sync.aligned.m8n8.x4.shared.b16 {%0,%1,%2,%3}, [%4];"
        : "=r"(a[0]), "=r"(a[1]), "=r"(a[2]), "=r"(a[3]) : "r"(addr));
}

__device__ __forceinline__ void initacc(float acc[2][4][4], const float* bias,
                                        int n0, int t) {
    #pragma unroll
    for (int j = 0; j < 4; j++) {
        float b0 = bias[n0 + 8 * j + 2 * t];
        float b1 = bias[n0 + 8 * j + 2 * t + 1];
        #pragma unroll
        for (int m = 0; m < 2; m++) {
            acc[m][j][0] = b0; acc[m][j][1] = b1;
            acc[m][j][2] = b0; acc[m][j][3] = b1;
        }
    }
}
__device__ __forceinline__ void zeroacc(float acc[2][4][4]) {
    #pragma unroll
    for (int m = 0; m < 2; m++)
        #pragma unroll
        for (int j = 0; j < 4; j++)
            #pragma unroll
            for (int c = 0; c < 4; c++) acc[m][j][c] = 0.f;
}

// warp GEMM: rows 0..31 x cols [n0abs, n0abs+32); weights fragment-permuted.
__device__ __forceinline__ void mma_gemm(float acc[2][4][4],
    const __half* __restrict__ hIn, const int kdim,
    const uint* __restrict__ Wp, const int ncols, int n0abs, int lane)
{
    const int nk = kdim >> 4;
    const int t = lane & 3, g = lane >> 2;
    const int row_in = (lane & 7) + ((lane >> 3) & 1) * 8;
    const int k_in = ((lane >> 4) & 1) * 8;
    const __half* aptr = hIn + row_in * LDH + k_in;
    const uint* wb  = Wp + ((size_t)t * (ncols >> 5) + (n0abs >> 5)) * 32 + g * 4;
    const uint* wb2 = wb + (size_t)4 * ncols;       // rows t+4
    const int wstep = ncols * 8;                    // 8 k-pairs per k16 step
    #pragma unroll 2
    for (int kk = 0; kk < nk; kk++) {
        uint4 B0 = *(const uint4*)wb;
        uint4 B1 = *(const uint4*)wb2;
        uint a0[4], a1[4];
        ldsm4(a0, aptr);
        ldsm4(a1, aptr + 16 * LDH);
        wb += wstep; wb2 += wstep; aptr += 16;
        mma16816(acc[0][0], a0[0], a0[1], a0[2], a0[3], B0.x, B1.x);
        mma16816(acc[1][0], a1[0], a1[1], a1[2], a1[3], B0.x, B1.x);
        mma16816(acc[0][1], a0[0], a0[1], a0[2], a0[3], B0.y, B1.y);
        mma16816(acc[1][1], a1[0], a1[1], a1[2], a1[3], B0.y, B1.y);
        mma16816(acc[0][2], a0[0], a0[1], a0[2], a0[3], B0.z, B1.z);
        mma16816(acc[1][2], a1[0], a1[1], a1[2], a1[3], B0.z, B1.z);
        mma16816(acc[0][3], a0[0], a0[1], a0[2], a0[3], B0.w, B1.w);
        mma16816(acc[1][3], a1[0], a1[1], a1[2], a1[3], B0.w, B1.w);
    }
}

__device__ __forceinline__ void storeacc_h(const float acc[2][4][4],
    __half* hOut, int n0, int g, int t, bool doGelu)
{
    #pragma unroll
    for (int m = 0; m < 2; m++) {
        int r0 = 16 * m + g;
        #pragma unroll
        for (int j = 0; j < 4; j++) {
            int c = n0 + 8 * j + 2 * t;
            float v0 = acc[m][j][0], v1 = acc[m][j][1];
            float v2 = acc[m][j][2], v3 = acc[m][j][3];
            if (doGelu) { v0 = gelu_f(v0); v1 = gelu_f(v1); v2 = gelu_f(v2); v3 = gelu_f(v3); }
            *(uint*)(hOut + r0 * LDH + c) = f2h2(v0, v1);
            *(uint*)(hOut + (r0 + 8) * LDH + c) = f2h2(v2, v3);
        }
    }
}

__device__ __forceinline__ void storeacc_f(const float acc[2][4][4],
    float* fOut, int n0, int g, int t)
{
    #pragma unroll
    for (int m = 0; m < 2; m++) {
        int r0 = 16 * m + g;
        #pragma unroll
        for (int j = 0; j < 4; j++) {
            int c = n0 + 8 * j + 2 * t;
            *(float2*)(fOut + r0 * SS + c) = make_float2(acc[m][j][0], acc[m][j][1]);
            *(float2*)(fOut + (r0 + 8) * SS + c) = make_float2(acc[m][j][2], acc[m][j][3]);
        }
    }
}

__device__ __forceinline__ void addacc_f(const float acc[2][4][4],
    float* fOut, int n0, int g, int t)
{
    #pragma unroll
    for (int m = 0; m < 2; m++) {
        int r0 = 16 * m + g;
        #pragma unroll
        for (int j = 0; j < 4; j++) {
            int c = n0 + 8 * j + 2 * t;
            float2* p0 = (float2*)(fOut + r0 * SS + c);
            float2* p1 = (float2*)(fOut + (r0 + 8) * SS + c);
            float2 u0 = *p0, u1 = *p1;
            u0.x += acc[m][j][0]; u0.y += acc[m][j][1];
            u1.x += acc[m][j][2]; u1.y += acc[m][j][3];
            *p0 = u0; *p1 = u1;
        }
    }
}

// ---- warp LayerNorm over 256 floats -> fp16 dst; lane owns cols lane*8..+7 ----
template <typename SRC>
__device__ __forceinline__ void warp_ln_h(const SRC* __restrict__ src,
                                          __half* __restrict__ dst,
                                          const float* __restrict__ gam,
                                          const float* __restrict__ bet, int lane) {
    float v[8];
    #pragma unroll
    for (int i = 0; i < 8; i++) v[i] = (float)src[lane * 8 + i];
    float s = 0.f;
    #pragma unroll
    for (int i = 0; i < 8; i++) s += v[i];
    #pragma unroll
    for (int o = 16; o; o >>= 1) s += __shfl_xor_sync(0xffffffffu, s, o);
    float mu = s * (1.f / HH);
    float q = 0.f;
    #pragma unroll
    for (int i = 0; i < 8; i++) { float d = v[i] - mu; q += d * d; }
    #pragma unroll
    for (int o = 16; o; o >>= 1) q += __shfl_xor_sync(0xffffffffu, q, o);
    float rs = rsqrtf(q * (1.f / HH) + 1e-5f);
    uint4 pack;
    float o0 = (v[0] - mu) * rs * gam[lane * 8 + 0] + bet[lane * 8 + 0];
    float o1 = (v[1] - mu) * rs * gam[lane * 8 + 1] + bet[lane * 8 + 1];
    float o2 = (v[2] - mu) * rs * gam[lane * 8 + 2] + bet[lane * 8 + 2];
    float o3 = (v[3] - mu) * rs * gam[lane * 8 + 3] + bet[lane * 8 + 3];
    float o4 = (v[4] - mu) * rs * gam[lane * 8 + 4] + bet[lane * 8 + 4];
    float o5 = (v[5] - mu) * rs * gam[lane * 8 + 5] + bet[lane * 8 + 5];
    float o6 = (v[6] - mu) * rs * gam[lane * 8 + 6] + bet[lane * 8 + 6];
    float o7 = (v[7] - mu) * rs * gam[lane * 8 + 7] + bet[lane * 8 + 7];
    pack.x = f2h2(o0, o1); pack.y = f2h2(o2, o3);
    pack.z = f2h2(o4, o5); pack.w = f2h2(o6, o7);
    *(uint4*)(dst + lane * 8) = pack;
}

// ---------------- fused weight repack (fp32 -> permuted half2 k-pairs) --------
__device__ __forceinline__ void rp_seg(const float* __restrict__ src,
                                       uint* __restrict__ dst, int rows2, int cols) {
    int idx = blockIdx.x * blockDim.x + threadIdx.x;
    int total = rows2 * cols;
    int stride = gridDim.x * blockDim.x;
    for (; idx < total; idx += stride) {
        int kp = idx / cols, col = idx - kp * cols;
        dst[(size_t)kp * cols + cperm(col)] =
            f2h2(src[(size_t)(2 * kp) * cols + col],
                 src[(size_t)(2 * kp + 1) * cols + col]);
    }
}

__global__ void repack_all(
    const float* We, const float* Wn, const float* Wm, const float* Wq,
    const float* Wo, const float* w1n, const float* w2n,
    const float* w1e, const float* w2e)
{
    switch (blockIdx.y) {
        case 0: rp_seg(We,  g_wph + OFF_WE,   512, 256); break;
        case 1: rp_seg(Wn,  g_wph + OFF_WN,  2048, 256); break;
        case 2: rp_seg(Wm,  g_wph + OFF_WM,  2048, 256); break;
        case 3: rp_seg(Wq,  g_wph + OFF_WQKV,1024, 768); break;
        case 4: rp_seg(Wo,  g_wph + OFF_WO,  1024, 256); break;
        case 5: rp_seg(w1n, g_wph + OFF_W1N, 1024, 512); break;
        case 6: rp_seg(w2n, g_wph + OFF_W2N, 2048, 256); break;
        case 7: rp_seg(w1e, g_wph + OFF_W1E, 1024, 512); break;
        case 8: rp_seg(w2e, g_wph + OFF_W2E, 2048, 256); break;
    }
}

// ---------------- zero output ----------------
__global__ void zero_kernel(float4* __restrict__ p, int n4) {
    int idx = blockIdx.x * blockDim.x + threadIdx.x;
    int stride = gridDim.x * blockDim.x;
    float4 z = make_float4(0.f, 0.f, 0.f, 0.f);
    for (; idx < n4; idx += stride) p[idx] = z;
}

// ---------------- gating kernel ----------------
__global__ void gate_kernel(const float* __restrict__ nf, const float* __restrict__ wg) {
    int n = blockIdx.x;
    int tid = threadIdx.x;
    float x = nf[n * HH + tid];
    float p[NE];
    #pragma unroll
    for (int e = 0; e < NE; e++) p[e] = x * wg[tid * NE + e];
    #pragma unroll
    for (int e = 0; e < NE; e++)
        #pragma unroll
        for (int o = 16; o; o >>= 1) p[e] += __shfl_xor_sync(0xffffffffu, p[e], o);
    __shared__ float logits[NE];
    if (tid < NE) logits[tid] = 0.f;
    __syncthreads();
    if ((tid & 31) == 0) {
        #pragma unroll
        for (int e = 0; e < NE; e++) atomicAdd(&logits[e], p[e]);
    }
    __syncthreads();
    if (tid == 0) {
        float v0 = -1e30f, v1 = -1e30f; int i0 = 0, i1 = 0;
        for (int e = 0; e < NE; e++) {
            float v = logits[e];
            if (v > v0) { v1 = v0; i1 = i0; v0 = v; i0 = e; }
            else if (v > v1) { v1 = v; i1 = e; }
        }
        float e1 = __expf(v1 - v0);
        float g0 = 1.f / (1.f + e1);
        g_te[n * 2 + 0] = i0; g_te[n * 2 + 1] = i1;
        g_tg[n * 2 + 0] = g0; g_tg[n * 2 + 1] = 1.f - g0;
    }
}

// ---------------- main kernel: one CTA (256 thr) per (node, slot) ----------------
__global__ __launch_bounds__(256, 2) void moe_kernel(
    const float* __restrict__ node_features,
    const float* __restrict__ edge_features,
    const float* __restrict__ edge_raw,
    const int*   __restrict__ neighbor_list,
    const float* __restrict__ neighbor_mask,
    const float* __restrict__ attn_mask,
    const float* __restrict__ b_edge, const float* __restrict__ b_node,
    const float* __restrict__ b_msg,  const float* __restrict__ b_qkv,
    const float* __restrict__ b_out,
    const float* __restrict__ lag_, const float* __restrict__ lab_,
    const float* __restrict__ lfg_, const float* __restrict__ lfb_,
    const float* __restrict__ b1n, const float* __restrict__ b2n,
    const float* __restrict__ b1e, const float* __restrict__ b2e,
    float* __restrict__ out)
{
    extern __shared__ float sm[];
    float* fC   = sm;                          // KK*SS fp32 tile
    float* sNh  = fC + KK * SS;                // HH
    float* sVec = sNh + HH;                    // HH
    float* sHn  = sVec + HH;                   // FF
    float* sMsk = sHn + FF;                    // KK
    float* sAm  = sMsk + KK;                   // KK
    float* sRed = sAm + KK;                    // 8
    __half* hA = (__half*)(sRed + 8);          // KK*LDH halfs
    __half* hB = hA + KK * LDH;
    __half* hC = hB + KK * LDH;

    const int n = blockIdx.x;
    const int slot = blockIdx.y;
    const int tid = threadIdx.x;
    const int lane = tid & 31, wid = tid >> 5;
    const int j = tid;
    const int g = lane >> 2, t = lane & 3;     // mma fragment coords
    const int n0 = wid * 32;                   // warp col range

    const int e = g_te[n * 2 + slot];
    const float gate = g_tg[n * 2 + slot];
    const float* lag = lag_ + e * HH;
    const float* lab = lab_ + e * HH;
    const float* lfg = lfg_ + e * HH;
    const float* lfb = lfb_ + e * HH;

    if (tid < KK) {
        sMsk[tid] = neighbor_mask[n * KK + tid];
        sAm[tid]  = attn_mask[n * KK + tid];
    }
    __syncthreads();
    float cnt = 0.f;
    #pragma unroll
    for (int k = 0; k < KK; k++) cnt += sMsk[k];
    float inv_cnt = 1.f / (cnt + 1e-5f);

    const float xj = node_features[(size_t)n * HH + j];

    // ---- recv layernorm -> sNh (fp32) ----
    {
        float s = bsum256(xj, sRed);
        float mu = s * (1.f / HH);
        float d = xj - mu;
        float q = bsum256(d * d, sRed);
        float rs = rsqrtf(q * (1.f / HH) + 1e-5f);
        sNh[j] = d * rs * lag[j] + lab[j];
    }
    __syncthreads();

    // ---- edge_raw -> hA (32x128 fp16) ----
    {
        const float4* src = (const float4*)(edge_raw + (size_t)n * KK * DEn);
        #pragma unroll
        for (int i = 0; i < 4; i++) {
            int idx = tid + 256 * i;          // float4 idx; 32 per row
            float4 v = src[idx];
            int row = idx >> 5, c4 = (idx & 31) * 4;
            uint2 h; h.x = f2h2(v.x, v.y); h.y = f2h2(v.z, v.w);
            *(uint2*)(hA + row * LDH + c4) = h;
        }
    }
    // ---- rv = recv @ Wn_bottom + bn -> sVec (GEMV, permuted col) ----
    {
        const uint* W = g_wph + OFF_WN + (size_t)e * 65536u + 128u * 256u + cperm(j);
        ull a0 = pk2(b_node[e * HH + j], 0.f);
        ull a1 = pk2(0.f, 0.f), a2 = pk2(0.f, 0.f), a3 = pk2(0.f, 0.f);
        #pragma unroll 8
        for (int i = 0; i < 128; i += 4) {
            fma2(a0, *(const ull*)(sNh + 2 * i),     h2f2(W[(size_t)i * 256]));
            fma2(a1, *(const ull*)(sNh + 2 * i + 2), h2f2(W[(size_t)(i + 1) * 256]));
            fma2(a2, *(const ull*)(sNh + 2 * i + 4), h2f2(W[(size_t)(i + 2) * 256]));
            fma2(a3, *(const ull*)(sNh + 2 * i + 6), h2f2(W[(size_t)(i + 3) * 256]));
        }
        sVec[j] = fold(a0) + fold(a1) + fold(a2) + fold(a3);
    }
    __syncthreads();

    // ---- eh = gelu(edge_raw(hA) @ We + be) -> hB ----
    {
        float acc[2][4][4];
        initacc(acc, b_edge + e * HH, n0, t);
        mma_gemm(acc, hA, DEn, g_wph + OFF_WE + (size_t)e * 16384u, 256, n0, lane);
        storeacc_h(acc, hB, n0, g, t, true);
    }
    __syncthreads();

    // ---- sender = LN(node_features[nbr]) -> hA ----
    for (int k = wid; k < KK; k += 8) {
        int nbr = neighbor_list[n * KK + k];
        warp_ln_h(node_features + (size_t)nbr * HH, hA + k * LDH, lag, lab, lane);
    }
    __syncthreads();

    // ---- nodeh = gelu(sender(hA)@Wn_top + rv) -> hC ----
    {
        float acc[2][4][4];
        initacc(acc, sVec, n0, t);
        mma_gemm(acc, hA, HH, g_wph + OFF_WN + (size_t)e * 65536u, 256, n0, lane);
        storeacc_h(acc, hC, n0, g, t, true);
    }
    __syncthreads();

    // ---- msg = gelu(eh(hB)@Wm_top + nodeh(hC)@Wm_bot + bm) -> hA ----
    {
        const uint* Wt = g_wph + OFF_WM + (size_t)e * 65536u;
        float acc[2][4][4];
        initacc(acc, b_msg + e * HH, n0, t);
        mma_gemm(acc, hB, HH, Wt, 256, n0, lane);
        mma_gemm(acc, hC, HH, Wt + 128u * 256u, 256, n0, lane);
        storeacc_h(acc, hA, n0, g, t, true);
    }
    __syncthreads();

    // ---- qkv from msg(hA): q->hB, k->hC, v->hA (in-place after barrier) ----
    {
        const uint* W = g_wph + OFF_WQKV + (size_t)e * 98304u;
        const float* bq = b_qkv + e * 3 * HH;
        {
            float acc[2][4][4];
            initacc(acc, bq, n0, t);
            mma_gemm(acc, hA, HH, W, 768, n0, lane);
            storeacc_h(acc, hB, n0, g, t, false);
        }
        {
            float acc[2][4][4];
            initacc(acc, bq + 256, n0, t);
            mma_gemm(acc, hA, HH, W, 768, n0 + 256, lane);
            storeacc_h(acc, hC, n0, g, t, false);
        }
        {
            float acc[2][4][4];
            initacc(acc, bq + 512, n0, t);
            mma_gemm(acc, hA, HH, W, 768, n0 + 512, lane);
            __syncthreads();                  // all reads of msg complete
            storeacc_h(acc, hA, n0, g, t, false);
        }
    }
    __syncthreads();

    // ---- attention: warp = head, lane = query. q(hB), k(hC), v(hA) -> hB in place ----
    {
        const int h = wid;
        const int a = lane;
        const __half* qp = hB + a * LDH + h * DHn;
        ull qv[16];
        #pragma unroll
        for (int i = 0; i < 4; i++) {
            uint4 u = *(const uint4*)(qp + 8 * i);
            qv[4 * i + 0] = h2f2(u.x); qv[4 * i + 1] = h2f2(u.y);
            qv[4 * i + 2] = h2f2(u.z); qv[4 * i + 3] = h2f2(u.w);
        }
        float sc[KK];
        const float scale = 0.17677669529663687f;   // 1/sqrt(32)
        #pragma unroll
        for (int b = 0; b < KK; b++) {
            const __half* kp = hC + b * LDH + h * DHn;
            ull d0 = pk2(0.f, 0.f), d1 = pk2(0.f, 0.f);
            #pragma unroll
            for (int i = 0; i < 4; i++) {
                uint4 u = *(const uint4*)(kp + 8 * i);
                fma2(d0, qv[4 * i + 0], h2f2(u.x));
                fma2(d1, qv[4 * i + 1], h2f2(u.y));
                fma2(d0, qv[4 * i + 2], h2f2(u.z));
                fma2(d1, qv[4 * i + 3], h2f2(u.w));
            }
            sc[b] = (fold(d0) + fold(d1)) * scale + sAm[b];
        }
        float m = sc[0];
        #pragma unroll
        for (int b = 1; b < KK; b++) m = fmaxf(m, sc[b]);
        float ssum = 0.f;
        #pragma unroll
        for (int b = 0; b < KK; b++) { sc[b] = __expf(sc[b] - m); ssum += sc[b]; }
        float inv = 1.f / ssum;
        ull o[16];
        #pragma unroll
        for (int i = 0; i < 16; i++) o[i] = pk2(0.f, 0.f);
        #pragma unroll
        for (int b = 0; b < KK; b++) {
            float p = sc[b] * inv;
            ull pp = pk2(p, p);
            const __half* vp = hA + b * LDH + h * DHn;
            #pragma unroll
            for (int i = 0; i < 4; i++) {
                uint4 u = *(const uint4*)(vp + 8 * i);
                fma2(o[4 * i + 0], pp, h2f2(u.x));
                fma2(o[4 * i + 1], pp, h2f2(u.y));
                fma2(o[4 * i + 2], pp, h2f2(u.z));
                fma2(o[4 * i + 3], pp, h2f2(u.w));
            }
        }
        // in-place store over q row (only this lane reads it)
        __half* op = hB + a * LDH + h * DHn;
        #pragma unroll
        for (int i = 0; i < 16; i++) {
            float lo, hi; upk2(o[i], lo, hi);
            *(uint*)(op + 2 * i) = f2h2(lo, hi);
        }
    }
    __syncthreads();

    // ---- edge_out = attn_out(hB) @ Wo + bo -> fC (fp32) ----
    {
        float acc[2][4][4];
        initacc(acc, b_out + e * HH, n0, t);
        mma_gemm(acc, hB, HH, g_wph + OFF_WO + (size_t)e * 32768u, 256, n0, lane);
        storeacc_f(acc, fC, n0, g, t);
    }
    __syncthreads();

    // ---- masked-mean aggregate -> nfj ----
    float nfj;
    {
        float s = 0.f;
        #pragma unroll
        for (int k = 0; k < KK; k++) s += fC[k * SS + j] * sMsk[k];
        nfj = s * inv_cnt + xj;
    }
    __syncthreads();
    // ---- ef = edge_out + edge_features (RMW fC) ----
    {
        const float4* efsrc = (const float4*)(edge_features + (size_t)n * KK * HH);
        #pragma unroll
        for (int i = 0; i < 8; i++) {
            int idx = tid + 256 * i;           // float4 idx, 64 per row
            int row = idx >> 6, c4 = (idx & 63) * 4;
            float4* d4 = (float4*)(fC + row * SS + c4);
            float4 v = *d4;
            float4 a = efsrc[idx];
            v.x += a.x; v.y += a.y; v.z += a.z; v.w += a.w;
            *d4 = v;
        }
    }
    __syncthreads();

    // ---- node FFN LN -> sVec ----
    {
        float s = bsum256(nfj, sRed);
        float mu = s * (1.f / HH);
        float d = nfj - mu;
        float q = bsum256(d * d, sRed);
        float rs = rsqrtf(q * (1.f / HH) + 1e-5f);
        sVec[j] = d * rs * lfg[j] + lfb[j];
    }
    __syncthreads();
    // ---- W1n GEMV: 2 outputs per thread (permuted cols) ----
    {
        const int cp = cperm(tid);
        const uint* W = g_wph + OFF_W1N + (size_t)e * 65536u;
        ull a0 = pk2(b1n[e * FF + tid], 0.f), a1 = pk2(0.f, 0.f);
        ull c0 = pk2(b1n[e * FF + tid + 256], 0.f), c1 = pk2(0.f, 0.f);
        #pragma unroll 8
        for (int i = 0; i < 128; i += 2) {
            ull x0 = *(const ull*)(sVec + 2 * i);
            ull x1 = *(const ull*)(sVec + 2 * i + 2);
            fma2(a0, x0, h2f2(W[(size_t)i * 512 + cp]));
            fma2(c0, x0, h2f2(W[(size_t)i * 512 + cp + 256]));
            fma2(a1, x1, h2f2(W[(size_t)(i + 1) * 512 + cp]));
            fma2(c1, x1, h2f2(W[(size_t)(i + 1) * 512 + cp + 256]));
        }
        sHn[tid]       = gelu_f(fold(a0) + fold(a1));
        sHn[tid + 256] = gelu_f(fold(c0) + fold(c1));
    }
    __syncthreads();
    // ---- W2n GEMV -> node_final (permuted col) ----
    float node_final;
    {
        const uint* W = g_wph + OFF_W2N + (size_t)e * 65536u + cperm(j);
        ull a0 = pk2(b2n[e * HH + j], 0.f);
        ull a1 = pk2(0.f, 0.f), a2 = pk2(0.f, 0.f), a3 = pk2(0.f, 0.f);
        #pragma unroll 8
        for (int i = 0; i < 256; i += 4) {
            fma2(a0, *(const ull*)(sHn + 2 * i),     h2f2(W[(size_t)i * 256]));
            fma2(a1, *(const ull*)(sHn + 2 * i + 2), h2f2(W[(size_t)(i + 1) * 256]));
            fma2(a2, *(const ull*)(sHn + 2 * i + 4), h2f2(W[(size_t)(i + 2) * 256]));
            fma2(a3, *(const ull*)(sHn + 2 * i + 6), h2f2(W[(size_t)(i + 3) * 256]));
        }
        node_final = nfj + fold(a0) + fold(a1) + fold(a2) + fold(a3);
    }

    // ---- edge FFN: eh2 = LN(ef(fC)) -> hA ----
    for (int k = wid; k < KK; k += 8) {
        warp_ln_h(fC + k * SS, hA + k * LDH, lfg, lfb, lane);
    }
    __syncthreads();

    // ---- hidden0 = gelu(eh2(hA)@W1e[:, :256]) -> hB ----
    {
        float acc[2][4][4];
        initacc(acc, b1e + e * FF, n0, t);
        mma_gemm(acc, hA, HH, g_wph + OFF_W1E + (size_t)e * 65536u, 512, n0, lane);
        storeacc_h(acc, hB, n0, g, t, true);
    }
    __syncthreads();
    // ---- fC += b2e + hidden0(hB) @ W2e_top ----
    {
        float acc[2][4][4];
        initacc(acc, b2e + e * HH, n0, t);
        mma_gemm(acc, hB, HH, g_wph + OFF_W2E + (size_t)e * 65536u, 256, n0, lane);
        addacc_f(acc, fC, n0, g, t);
    }
    __syncthreads();
    // ---- hidden1 = gelu(eh2(hA)@W1e[:, 256:]) -> hB ----
    {
        float acc[2][4][4];
        initacc(acc, b1e + e * FF + 256, n0, t);
        mma_gemm(acc, hA, HH, g_wph + OFF_W1E + (size_t)e * 65536u, 512, n0 + 256, lane);
        storeacc_h(acc, hB, n0, g, t, true);
    }
    __syncthreads();
    // ---- final = fC + hidden1(hB)@W2e_bot ; atomic write ----
    {
        float acc[2][4][4];
        zeroacc(acc);
        mma_gemm(acc, hB, HH, g_wph + OFF_W2E + (size_t)e * 65536u + 128u * 256u,
                 256, n0, lane);
        float* eout = out + (size_t)NN * HH + (size_t)n * KK * HH;
        #pragma unroll
        for (int m = 0; m < 2; m++) {
            #pragma unroll
            for (int jj = 0; jj < 4; jj++) {
                int c = n0 + 8 * jj + 2 * t;
                int r0 = 16 * m + g, r1 = r0 + 8;
                atomicAdd(eout + (size_t)r0 * HH + c,
                          gate * (fC[r0 * SS + c] + acc[m][jj][0]));
                atomicAdd(eout + (size_t)r0 * HH + c + 1,
                          gate * (fC[r0 * SS + c + 1] + acc[m][jj][1]));
                atomicAdd(eout + (size_t)r1 * HH + c,
                          gate * (fC[r1 * SS + c] + acc[m][jj][2]));
                atomicAdd(eout + (size_t)r1 * HH + c + 1,
                          gate * (fC[r1 * SS + c + 1] + acc[m][jj][3]));
            }
        }
    }
    atomicAdd(out + (size_t)n * HH + j, gate * node_final);
}

static constexpr int SMEM_BYTES =
    (KK * SS + HH + HH + FF + KK + KK + 8) * 4 + 3 * KK * LDH * 2;

extern "C" void kernel_launch(void* const* d_in, const int* in_sizes, int n_in,
                              void* d_out, int out_size) {
    const float* node_features = (const float*)d_in[0];
    const float* edge_features = (const float*)d_in[1];
    const float* edge_raw      = (const float*)d_in[2];
    const int*   neighbor_list = (const int*)  d_in[3];
    const float* neighbor_mask = (const float*)d_in[4];
    const float* attn_mask     = (const float*)d_in[5];
    const float* w_gate        = (const float*)d_in[6];
    const float* W_edge = (const float*)d_in[7];
    const float* b_edge = (const float*)d_in[8];
    const float* W_node = (const float*)d_in[9];
    const float* b_node = (const float*)d_in[10];
    const float* W_msg  = (const float*)d_in[11];
    const float* b_msg  = (const float*)d_in[12];
    const float* W_qkv  = (const float*)d_in[13];
    const float* b_qkv  = (const float*)d_in[14];
    const float* W_out  = (const float*)d_in[15];
    const float* b_out  = (const float*)d_in[16];
    const float* lag    = (const float*)d_in[17];
    const float* lab    = (const float*)d_in[18];
    const float* lfg    = (const float*)d_in[19];
    const float* lfb    = (const float*)d_in[20];
    const float* W1n = (const float*)d_in[21];
    const float* b1n = (const float*)d_in[22];
    const float* W2n = (const float*)d_in[23];
    const float* b2n = (const float*)d_in[24];
    const float* W1e = (const float*)d_in[25];
    const float* b1e = (const float*)d_in[26];
    const float* W2e = (const float*)d_in[27];
    const float* b2e = (const float*)d_in[28];
    float* out = (float*)d_out;

    cudaFuncSetAttribute(moe_kernel, cudaFuncAttributeMaxDynamicSharedMemorySize, SMEM_BYTES);

    dim3 rg(128, 9);
    repack_all<<<rg, 256>>>(W_edge, W_node, W_msg, W_qkv, W_out, W1n, W2n, W1e, W2e);
    gate_kernel<<<NN, 256>>>(node_features, w_gate);
    zero_kernel<<<512, 256>>>((float4*)out, out_size / 4);

    dim3 grid(NN, 2);
    moe_kernel<<<grid, 256, SMEM_BYTES>>>(
        node_features, edge_features, edge_raw, neighbor_list, neighbor_mask,
        attn_mask, b_edge, b_node, b_msg, b_qkv, b_out,
        lag, lab, lfg, lfb, b1n, b2n, b1e, b2e, out);
}